// round 16
// baseline (speedup 1.0000x reference)
#include <cuda_runtime.h>
#include <cuda_bf16.h>

// DiffIOU: BS=64 polygons, NV=128 vertices, DIM=512, 4 mask channels.
// One CTA per batch, one thread per vertex.
// R2: loads hoisted above all barriers; reductions fused via warp shuffles
//     (2 barriers total instead of 56).

#define BS 64
#define NV 128
#define DIMI 512
#define DIMF 512.0f
#define FULL 0xFFFFFFFFu

__device__ __forceinline__ float fsign(float d) {
    return (d > 0.0f) ? 1.0f : ((d < 0.0f) ? -1.0f : 0.0f);
}

__global__ void __launch_bounds__(NV, 8)
diffiou_kernel(const float2* __restrict__ pred_points,
               const float2* __restrict__ gt_points,
               const float*  __restrict__ gt_mask,
               float* __restrict__ out) {
    __shared__ float smax[4][2];   // per-warp partial maxes (py, gy)
    __shared__ float ssum[4][6];   // per-warp partial sums

    const int b    = blockIdx.x;
    const int v    = threadIdx.x;
    const int vn   = (v + 1) & (NV - 1);
    const int wid  = v >> 5;
    const int lane = v & 31;

    // ---- load + scale points (issue all global loads first) ----
    float2 p  = __ldg(&pred_points[b * NV + v]);
    float2 pn = __ldg(&pred_points[b * NV + vn]);
    float2 g  = __ldg(&gt_points[b * NV + v]);
    float2 gn = __ldg(&gt_points[b * NV + vn]);

    float px = p.x * DIMF,  py = p.y * DIMF;
    float nx = pn.x * DIMF, ny = pn.y * DIMF;
    float gx = g.x * DIMF,  gy = g.y * DIMF;
    float gnx = gn.x * DIMF, gny = gn.y * DIMF;

    // ---- bilinear gather indices + issue all 16 mask loads NOW ----
    float X0f = floorf(px), Y0f = floorf(py);
    float X1f = X0f + 1.0f, Y1f = Y0f + 1.0f;

    int X0 = (int)fminf(fmaxf(X0f, 0.0f), DIMF - 1.0f);
    int X1 = (int)fminf(fmaxf(X1f, 0.0f), DIMF - 1.0f);
    int Y0 = (int)fminf(fmaxf(Y0f, 0.0f), DIMF - 1.0f);
    int Y1 = (int)fminf(fmaxf(Y1f, 0.0f), DIMF - 1.0f);

    const float* mb = gt_mask + (size_t)b * 4 * DIMI * DIMI;

    float M00[4], M01[4], M10[4], M11[4];
    #pragma unroll
    for (int c = 0; c < 4; c++) {
        const float* mc = mb + (size_t)c * DIMI * DIMI;
        M00[c] = __ldg(&mc[Y0 * DIMI + X0]);
        M01[c] = __ldg(&mc[Y1 * DIMI + X0]);
        M10[c] = __ldg(&mc[Y0 * DIMI + X1]);
        M11[c] = __ldg(&mc[Y1 * DIMI + X1]);
    }

    // ---- fused max reduction (py, gy) while loads are in flight ----
    float m0 = py, m1 = gy;
    #pragma unroll
    for (int off = 16; off > 0; off >>= 1) {
        m0 = fmaxf(m0, __shfl_xor_sync(FULL, m0, off));
        m1 = fmaxf(m1, __shfl_xor_sync(FULL, m1, off));
    }
    if (lane == 0) { smax[wid][0] = m0; smax[wid][1] = m1; }
    __syncthreads();                                    // barrier #1
    float ymax_p = fmaxf(fmaxf(smax[0][0], smax[1][0]),
                         fmaxf(smax[2][0], smax[3][0]));
    float ymax_g = fmaxf(fmaxf(smax[0][1], smax[1][1]),
                         fmaxf(smax[2][1], smax[3][1]));

    // ---- per-vertex terms ----
    float term_p = (nx - px) * (ymax_p - (ny + py) * 0.5f);
    float term_g = (gnx - gx) * (ymax_g - (gny + gy) * 0.5f);

    float fx = floorf(nx) - X0f;   // floor(nx) - floor(px)
    float fy = floorf(ny) - Y0f;
    if (v == 0) { fx = 1.0f; fy = 1.0f; }
    float sm_x = fsign(nx - px) * fminf(fabsf(fx), 1.0f);
    float sm_y = fsign(ny - py) * fminf(fabsf(fy), 1.0f);

    float w00 = (X1f - px) * (Y1f - py);
    float w01 = (X1f - px) * (py - Y0f);
    float w10 = (px - X0f) * (Y1f - py);
    float w11 = (px - X0f) * (py - Y0f);

    float r[6];
    r[0] = term_p;
    r[1] = term_g;
    #pragma unroll
    for (int c = 0; c < 4; c++) {
        float interp = w00 * M00[c] + w01 * M01[c] + w10 * M10[c] + w11 * M11[c];
        r[2 + c] = interp * ((c < 2) ? sm_x : sm_y);
    }

    // ---- fused 6-value sum reduction ----
    #pragma unroll
    for (int off = 16; off > 0; off >>= 1) {
        #pragma unroll
        for (int i = 0; i < 6; i++)
            r[i] += __shfl_xor_sync(FULL, r[i], off);
    }
    if (lane == 0) {
        #pragma unroll
        for (int i = 0; i < 6; i++) ssum[wid][i] = r[i];
    }
    __syncthreads();                                    // barrier #2

    if (v == 0) {
        float t[6];
        #pragma unroll
        for (int i = 0; i < 6; i++)
            t[i] = ssum[0][i] + ssum[1][i] + ssum[2][i] + ssum[3][i];
        float pred_area = fabsf(t[0]);
        float gt_area   = fabsf(t[1]);
        float int_area  = (fabsf(t[2]) + fabsf(t[3]) + fabsf(t[4]) + fabsf(t[5])) * 0.25f;
        float union_area = pred_area + gt_area - int_area;
        atomicAdd(out, (int_area / union_area) * (1.0f / (float)BS));
    }
}

extern "C" void kernel_launch(void* const* d_in, const int* in_sizes, int n_in,
                              void* d_out, int out_size) {
    const float2* pred = (const float2*)d_in[0];
    const float2* gt   = (const float2*)d_in[1];
    const float*  mask = (const float*)d_in[2];
    float* out = (float*)d_out;

    cudaMemsetAsync(out, 0, sizeof(float), 0);
    diffiou_kernel<<<BS, NV>>>(pred, gt, mask, out);
}

// round 17
// speedup vs baseline: 1.0445x; 1.0445x over previous
#include <cuda_runtime.h>
#include <cuda_bf16.h>

// DiffIOU: BS=64 polygons, NV=128 vertices, DIM=512, 4 mask channels.
// One CTA per batch, one thread per vertex.
// R2: loads hoisted above all barriers; reductions fused via warp shuffles
//     (2 barriers total instead of 56).

#define BS 64
#define NV 128
#define DIMI 512
#define DIMF 512.0f
#define FULL 0xFFFFFFFFu

__device__ __forceinline__ float fsign(float d) {
    return (d > 0.0f) ? 1.0f : ((d < 0.0f) ? -1.0f : 0.0f);
}

__global__ void __launch_bounds__(NV, 8)
diffiou_kernel(const float2* __restrict__ pred_points,
               const float2* __restrict__ gt_points,
               const float*  __restrict__ gt_mask,
               float* __restrict__ out) {
    __shared__ float smax[4][2];   // per-warp partial maxes (py, gy)
    __shared__ float ssum[4][6];   // per-warp partial sums

    const int b    = blockIdx.x;
    const int v    = threadIdx.x;
    const int vn   = (v + 1) & (NV - 1);
    const int wid  = v >> 5;
    const int lane = v & 31;

    // ---- load + scale points (issue all global loads first) ----
    float2 p  = __ldg(&pred_points[b * NV + v]);
    float2 pn = __ldg(&pred_points[b * NV + vn]);
    float2 g  = __ldg(&gt_points[b * NV + v]);
    float2 gn = __ldg(&gt_points[b * NV + vn]);

    float px = p.x * DIMF,  py = p.y * DIMF;
    float nx = pn.x * DIMF, ny = pn.y * DIMF;
    float gx = g.x * DIMF,  gy = g.y * DIMF;
    float gnx = gn.x * DIMF, gny = gn.y * DIMF;

    // ---- bilinear gather indices + issue all 16 mask loads NOW ----
    float X0f = floorf(px), Y0f = floorf(py);
    float X1f = X0f + 1.0f, Y1f = Y0f + 1.0f;

    int X0 = (int)fminf(fmaxf(X0f, 0.0f), DIMF - 1.0f);
    int X1 = (int)fminf(fmaxf(X1f, 0.0f), DIMF - 1.0f);
    int Y0 = (int)fminf(fmaxf(Y0f, 0.0f), DIMF - 1.0f);
    int Y1 = (int)fminf(fmaxf(Y1f, 0.0f), DIMF - 1.0f);

    const float* mb = gt_mask + (size_t)b * 4 * DIMI * DIMI;

    float M00[4], M01[4], M10[4], M11[4];
    #pragma unroll
    for (int c = 0; c < 4; c++) {
        const float* mc = mb + (size_t)c * DIMI * DIMI;
        M00[c] = __ldg(&mc[Y0 * DIMI + X0]);
        M01[c] = __ldg(&mc[Y1 * DIMI + X0]);
        M10[c] = __ldg(&mc[Y0 * DIMI + X1]);
        M11[c] = __ldg(&mc[Y1 * DIMI + X1]);
    }

    // ---- fused max reduction (py, gy) while loads are in flight ----
    float m0 = py, m1 = gy;
    #pragma unroll
    for (int off = 16; off > 0; off >>= 1) {
        m0 = fmaxf(m0, __shfl_xor_sync(FULL, m0, off));
        m1 = fmaxf(m1, __shfl_xor_sync(FULL, m1, off));
    }
    if (lane == 0) { smax[wid][0] = m0; smax[wid][1] = m1; }
    __syncthreads();                                    // barrier #1
    float ymax_p = fmaxf(fmaxf(smax[0][0], smax[1][0]),
                         fmaxf(smax[2][0], smax[3][0]));
    float ymax_g = fmaxf(fmaxf(smax[0][1], smax[1][1]),
                         fmaxf(smax[2][1], smax[3][1]));

    // ---- per-vertex terms ----
    float term_p = (nx - px) * (ymax_p - (ny + py) * 0.5f);
    float term_g = (gnx - gx) * (ymax_g - (gny + gy) * 0.5f);

    float fx = floorf(nx) - X0f;   // floor(nx) - floor(px)
    float fy = floorf(ny) - Y0f;
    if (v == 0) { fx = 1.0f; fy = 1.0f; }
    float sm_x = fsign(nx - px) * fminf(fabsf(fx), 1.0f);
    float sm_y = fsign(ny - py) * fminf(fabsf(fy), 1.0f);

    float w00 = (X1f - px) * (Y1f - py);
    float w01 = (X1f - px) * (py - Y0f);
    float w10 = (px - X0f) * (Y1f - py);
    float w11 = (px - X0f) * (py - Y0f);

    float r[6];
    r[0] = term_p;
    r[1] = term_g;
    #pragma unroll
    for (int c = 0; c < 4; c++) {
        float interp = w00 * M00[c] + w01 * M01[c] + w10 * M10[c] + w11 * M11[c];
        r[2 + c] = interp * ((c < 2) ? sm_x : sm_y);
    }

    // ---- fused 6-value sum reduction ----
    #pragma unroll
    for (int off = 16; off > 0; off >>= 1) {
        #pragma unroll
        for (int i = 0; i < 6; i++)
            r[i] += __shfl_xor_sync(FULL, r[i], off);
    }
    if (lane == 0) {
        #pragma unroll
        for (int i = 0; i < 6; i++) ssum[wid][i] = r[i];
    }
    __syncthreads();                                    // barrier #2

    if (v == 0) {
        float t[6];
        #pragma unroll
        for (int i = 0; i < 6; i++)
            t[i] = ssum[0][i] + ssum[1][i] + ssum[2][i] + ssum[3][i];
        float pred_area = fabsf(t[0]);
        float gt_area   = fabsf(t[1]);
        float int_area  = (fabsf(t[2]) + fabsf(t[3]) + fabsf(t[4]) + fabsf(t[5])) * 0.25f;
        float union_area = pred_area + gt_area - int_area;
        atomicAdd(out, (int_area / union_area) * (1.0f / (float)BS));
    }
}

extern "C" void kernel_launch(void* const* d_in, const int* in_sizes, int n_in,
                              void* d_out, int out_size) {
    const float2* pred = (const float2*)d_in[0];
    const float2* gt   = (const float2*)d_in[1];
    const float*  mask = (const float*)d_in[2];
    float* out = (float*)d_out;

    cudaMemsetAsync(out, 0, sizeof(float), 0);
    diffiou_kernel<<<BS, NV>>>(pred, gt, mask, out);
}